// round 2
// baseline (speedup 1.0000x reference)
#include <cuda_runtime.h>
#include <cuda_bf16.h>

#define B 16
#define H 512
#define W 512
#define IMG (H*W)              // 262144
#define KER 31
#define PAD 15

// Scratch (device globals — no cudaMalloc allowed)
__device__ float         g_hsum[B*IMG];      // horizontal 31-tap sums
__device__ unsigned char g_mask8[B*IMG];     // mask as 0/1 bytes
__device__ double        g_acc[B][4];        // [weit_sum, wbce_sum, inter, card]

// ---------------------------------------------------------------------------
// K1: per-row horizontal box sum + mask repack (+ zero accumulators)
// grid (H, B), block W threads
// ---------------------------------------------------------------------------
__global__ void k1_hsum(const int* __restrict__ mask)
{
    __shared__ float srow[W + 2*PAD];
    const int c = threadIdx.x;          // 0..511
    const int r = blockIdx.x;
    const int b = blockIdx.y;

    // zero accumulators once (block (0,0)); stream ordering guarantees K2 sees it
    if (blockIdx.x == 0 && blockIdx.y == 0 && c < B*4)
        ((double*)g_acc)[c] = 0.0;

    // pad halo with zeros
    if (c < 2*PAD) srow[(c < PAD) ? c : (W + c)] = 0.0f;

    const int mv = mask[b*IMG + r*W + c];
    const int m = (mv == 255) ? 0 : mv;        // 255 remap (never fires, cheap)
    const float mf = (float)m;
    srow[c + PAD] = mf;
    g_mask8[b*IMG + r*W + c] = (unsigned char)m;
    __syncthreads();

    float s = 0.0f;
    #pragma unroll
    for (int j = 0; j < KER; ++j) s += srow[c + j];
    g_hsum[b*IMG + r*W + c] = s;
}

// ---------------------------------------------------------------------------
// K2: vertical running sum + fused loss math + per-batch reduction
// grid (W/256, H/ROWS, B), block 256 threads
// ---------------------------------------------------------------------------
#define ROWS 64
__global__ void k2_main(const float* __restrict__ pred)
{
    const int c  = blockIdx.x * 256 + threadIdx.x;
    const int r0 = blockIdx.y * ROWS;
    const int b  = blockIdx.z;

    const float* hs = g_hsum + b*IMG + c;
    const unsigned char* m8 = g_mask8 + b*IMG + c;
    const float* p0p = pred + (size_t)(b*2    )*IMG + c;
    const float* p1p = pred + (size_t)(b*2 + 1)*IMG + c;

    // init vertical window sum for rows [r0-15, r0+15] clipped
    float vsum = 0.0f;
    {
        int lo = r0 - PAD; if (lo < 0) lo = 0;
        int hi = r0 + PAD; if (hi > H-1) hi = H-1;
        for (int rr = lo; rr <= hi; ++rr) vsum += hs[rr*W];
    }

    float a_w = 0.f, a_wb = 0.f, a_i = 0.f, a_c = 0.f;

    for (int r = r0; r < r0 + ROWS; ++r) {
        const float pooled = vsum * (1.0f / (KER*KER));
        const float mf = (float)m8[r*W];
        const float weit = 1.0f + 5.0f * fabsf(pooled - mf);

        const float d  = p1p[r*W] - p0p[r*W];          // logit diff
        const float t  = log1pf(__expf(-fabsf(d)));    // log1p(exp(-|d|))
        const float sp_pos = fmaxf(d, 0.0f) + t;       // softplus(d)  = -logp0
        const float sp_neg = fmaxf(-d, 0.0f) + t;      // softplus(-d) = -logp1
        const float wbce = (mf != 0.0f) ? sp_neg : sp_pos;
        const float p1 = 1.0f / (1.0f + __expf(-d));   // sigmoid(d)

        a_w  += weit;
        a_wb += weit * wbce;
        a_i  += p1 * mf * weit;
        a_c  += (p1 + mf) * weit;

        // slide window: add r+16, drop r-15
        const int ra = r + PAD + 1, rs = r - PAD;
        if (ra < H)  vsum += hs[ra*W];
        if (rs >= 0) vsum -= hs[rs*W];
    }

    // warp reduce, lane0 atomic to doubles
    #pragma unroll
    for (int off = 16; off > 0; off >>= 1) {
        a_w  += __shfl_down_sync(0xffffffffu, a_w,  off);
        a_wb += __shfl_down_sync(0xffffffffu, a_wb, off);
        a_i  += __shfl_down_sync(0xffffffffu, a_i,  off);
        a_c  += __shfl_down_sync(0xffffffffu, a_c,  off);
    }
    if ((threadIdx.x & 31) == 0) {
        atomicAdd(&g_acc[b][0], (double)a_w);
        atomicAdd(&g_acc[b][1], (double)a_wb);
        atomicAdd(&g_acc[b][2], (double)a_i);
        atomicAdd(&g_acc[b][3], (double)a_c);
    }
}

// ---------------------------------------------------------------------------
// K3: combine per-batch losses -> scalar mean
// ---------------------------------------------------------------------------
__global__ void k3_final(float* __restrict__ out)
{
    const int b = threadIdx.x;   // 32 threads, first 16 active
    double loss = 0.0;
    if (b < B) {
        const double w  = g_acc[b][0];
        const double wb = g_acc[b][1];
        const double it = g_acc[b][2];
        const double cd = g_acc[b][3];
        const double un = cd - it;
        loss = wb / w + (1.0 - (it + 1.0) / (un + 1.0));
    }
    #pragma unroll
    for (int off = 16; off > 0; off >>= 1)
        loss += __shfl_down_sync(0xffffffffu, loss, off);
    if (b == 0) out[0] = (float)(loss / (double)B);
}

extern "C" void kernel_launch(void* const* d_in, const int* in_sizes, int n_in,
                              void* d_out, int out_size)
{
    // Robust input selection: pred has 2*B*IMG elements, mask has B*IMG.
    const float* pred;
    const int*   mask;
    if (in_sizes[0] == 2*B*IMG) {
        pred = (const float*)d_in[0];
        mask = (const int*)d_in[1];
    } else {
        pred = (const float*)d_in[1];
        mask = (const int*)d_in[0];
    }
    float* out = (float*)d_out;
    (void)n_in; (void)out_size;

    k1_hsum<<<dim3(H, B), W>>>(mask);
    k2_main<<<dim3(W/256, H/ROWS, B), 256>>>(pred);
    k3_final<<<1, 32>>>(out);
}

// round 4
// speedup vs baseline: 2.4782x; 2.4782x over previous
#include <cuda_runtime.h>
#include <cuda_bf16.h>

#define B 16
#define H 512
#define W 512
#define IMG (H*W)
#define KER 31
#define PAD 15
#define HP (H + 2*PAD + 1)      // padded rows for hsum (zeros top/bottom, never written)
#define WPR 16                  // u32 words per row of packed mask bits

// Scratch (device globals — zero-initialized at load; padding rows stay zero)
__device__ unsigned char g_hsum8[B*HP*W];     // horizontal 31-tap popcounts (u8), row-padded
__device__ unsigned int  g_bits [B*H*WPR];    // packed mask bits
__device__ double        g_acc  [B][4];       // [weit_sum, wbce_sum, inter, card]

// ---------------------------------------------------------------------------
// K1: pack mask bits (ballot) + horizontal 31-tap sum via popcount
// grid (H, B), block 512
// ---------------------------------------------------------------------------
__global__ void k1_hsum(const int* __restrict__ mask)
{
    __shared__ unsigned int sbits[WPR + 2];   // [0]=0, [1..16]=row, [17]=0
    const int c = threadIdx.x;
    const int r = blockIdx.x;
    const int b = blockIdx.y;

    if (c == 0) { sbits[0] = 0; sbits[WPR + 1] = 0; }
    if (blockIdx.x == 0 && blockIdx.y == 0 && c < B*4)
        ((double*)g_acc)[c] = 0.0;

    const int mv = mask[(b*H + r)*W + c];
    const int m  = (mv == 255) ? 0 : mv;
    const unsigned int bal = __ballot_sync(0xffffffffu, m != 0);
    const int warp = c >> 5;
    if ((c & 31) == 0) {
        sbits[warp + 1] = bal;
        g_bits[(b*H + r)*WPR + warp] = bal;
    }
    __syncthreads();

    // window = columns [c-15, c+15]; padded bit position s = (c+32) - 15
    const int s = c + 17;
    const unsigned int lo = sbits[s >> 5];
    const unsigned int hi = sbits[(s >> 5) + 1];
    const unsigned int wnd = __funnelshift_r(lo, hi, s & 31);
    const int cnt = __popc(wnd & 0x7FFFFFFFu);   // 31 bits

    g_hsum8[(b*HP + r + PAD)*W + c] = (unsigned char)cnt;
}

// ---------------------------------------------------------------------------
// K2: vertical running sum (branch-free via zero padding) + fused loss math
// grid (W/256, H/ROWS, B), block 256
// ---------------------------------------------------------------------------
#define ROWS 32
__global__ void __launch_bounds__(256) k2_main(const float* __restrict__ pred)
{
    const int c  = blockIdx.x * 256 + threadIdx.x;
    const int r0 = blockIdx.y * ROWS;
    const int b  = blockIdx.z;

    // hs points at physical row 0 == logical row -PAD
    const unsigned char* hs = g_hsum8 + (size_t)b*HP*W + c;
    const unsigned int*  bw = g_bits  + (size_t)b*H*WPR + (c >> 5);
    const float* p0p = pred + (size_t)(2*b)*IMG + c;
    const float* p1p = p0p + IMG;
    const unsigned int sh = c & 31;

    // init: logical rows r0-15 .. r0+15 == physical rows r0 .. r0+30
    int vsum = 0;
    #pragma unroll
    for (int j = 0; j < KER; ++j)
        vsum += (int)hs[(r0 + j)*W];

    float a_w = 0.f, a_wb = 0.f, a_i = 0.f, a_c = 0.f;

    #pragma unroll 8
    for (int rr = 0; rr < ROWS; ++rr) {
        const int r = r0 + rr;
        const float pooled = (float)vsum * (1.0f/961.0f);
        const float mf = (float)((bw[r*WPR] >> sh) & 1u);
        const float weit = 1.0f + 5.0f * fabsf(pooled - mf);

        const float d = p1p[r*W] - p0p[r*W];
        const float e = __expf(-fabsf(d));           // exp(-|d|)
        const float t = __logf(1.0f + e);            // softplus tail
        const float wbce = fmaxf((mf != 0.f) ? -d : d, 0.0f) + t;
        const float p1 = ((d >= 0.f) ? 1.0f : e) * __fdividef(1.0f, 1.0f + e);

        a_w  += weit;
        a_wb += weit * wbce;
        a_i  += p1 * mf * weit;
        a_c  += (p1 + mf) * weit;

        // slide: add logical r+16 (phys r+KER), drop logical r-15 (phys r)
        vsum += (int)hs[(r + KER)*W] - (int)hs[r*W];
    }

    #pragma unroll
    for (int off = 16; off > 0; off >>= 1) {
        a_w  += __shfl_down_sync(0xffffffffu, a_w,  off);
        a_wb += __shfl_down_sync(0xffffffffu, a_wb, off);
        a_i  += __shfl_down_sync(0xffffffffu, a_i,  off);
        a_c  += __shfl_down_sync(0xffffffffu, a_c,  off);
    }
    if ((threadIdx.x & 31) == 0) {
        atomicAdd(&g_acc[b][0], (double)a_w);
        atomicAdd(&g_acc[b][1], (double)a_wb);
        atomicAdd(&g_acc[b][2], (double)a_i);
        atomicAdd(&g_acc[b][3], (double)a_c);
    }
}

// ---------------------------------------------------------------------------
// K3: combine per-batch losses -> scalar mean
// ---------------------------------------------------------------------------
__global__ void k3_final(float* __restrict__ out)
{
    const int b = threadIdx.x;
    double loss = 0.0;
    if (b < B) {
        const double w  = g_acc[b][0];
        const double wb = g_acc[b][1];
        const double it = g_acc[b][2];
        const double cd = g_acc[b][3];
        const double un = cd - it;
        loss = wb / w + (1.0 - (it + 1.0) / (un + 1.0));
    }
    #pragma unroll
    for (int off = 16; off > 0; off >>= 1)
        loss += __shfl_down_sync(0xffffffffu, loss, off);
    if (b == 0) out[0] = (float)(loss / (double)B);
}

extern "C" void kernel_launch(void* const* d_in, const int* in_sizes, int n_in,
                              void* d_out, int out_size)
{
    const float* pred;
    const int*   mask;
    if (in_sizes[0] == 2*B*IMG) {
        pred = (const float*)d_in[0];
        mask = (const int*)d_in[1];
    } else {
        pred = (const float*)d_in[1];
        mask = (const int*)d_in[0];
    }
    float* out = (float*)d_out;
    (void)n_in; (void)out_size;

    k1_hsum<<<dim3(H, B), W>>>(mask);
    k2_main<<<dim3(W/256, H/ROWS, B), 256>>>(pred);
    k3_final<<<1, 32>>>(out);
}

// round 5
// speedup vs baseline: 2.8714x; 1.1587x over previous
#include <cuda_runtime.h>
#include <cuda_bf16.h>

#define B 16
#define H 512
#define W 512
#define IMG (H*W)
#define KER 31
#define PAD 15
#define HP (H + 2*PAD + 1)      // padded rows for hsum (zeros top/bottom, never written)
#define WPR 16                  // u32 words per row of packed mask bits

// Scratch (device globals — zero-initialized at load; padding rows stay zero)
__device__ unsigned char g_hsum8[B*HP*W];     // horizontal 31-tap popcounts (u8), row-padded
__device__ unsigned int  g_bits [B*H*WPR];    // packed mask bits
__device__ double        g_acc  [B][4];       // [weit_sum, wbce_sum, inter, card]

// ---------------------------------------------------------------------------
// K1: pack mask bits (int4 + shfl-OR) + horizontal 31-tap popcount sum
// grid (H/4, B), block 512 (4 rows/block, 128 threads/row, 4 cols/thread)
// ---------------------------------------------------------------------------
__global__ void __launch_bounds__(512) k1_hsum(const int* __restrict__ mask)
{
    __shared__ unsigned int sbits[4][WPR + 2];   // [.][0]=0, [1..16]=row, [17]=0
    const int t   = threadIdx.x;
    const int rib = t >> 7;           // row in block 0..3
    const int q   = t & 127;          // column quad 0..127  (cols 4q..4q+3)
    const int r   = blockIdx.x*4 + rib;
    const int b   = blockIdx.y;

    if (blockIdx.x == 0 && blockIdx.y == 0 && t < B*4)
        ((double*)g_acc)[t] = 0.0;
    if (q == 0) sbits[rib][0] = 0;
    if (q == 1) sbits[rib][WPR + 1] = 0;

    // 4 mask values per thread
    const int4 mv = ((const int4*)mask)[(b*H + r)*(W/4) + q];
    const int m0 = (mv.x == 255) ? 0 : mv.x;
    const int m1 = (mv.y == 255) ? 0 : mv.y;
    const int m2 = (mv.z == 255) ? 0 : mv.z;
    const int m3 = (mv.w == 255) ? 0 : mv.w;
    unsigned int nib = (m0 ? 1u : 0u) | (m1 ? 2u : 0u) | (m2 ? 4u : 0u) | (m3 ? 8u : 0u);

    // assemble 32-bit word across 8-lane groups (each lane contributes a nibble)
    const int lane = t & 31;
    unsigned int v = nib << ((lane & 7) * 4);
    v |= __shfl_xor_sync(0xffffffffu, v, 1);
    v |= __shfl_xor_sync(0xffffffffu, v, 2);
    v |= __shfl_xor_sync(0xffffffffu, v, 4);
    if ((lane & 7) == 0) {
        const int widx = q >> 3;                  // word index in row, 0..15
        sbits[rib][widx + 1] = v;
        g_bits[(b*H + r)*WPR + widx] = v;
    }
    __syncthreads();

    // horizontal 31-tap popcount for 4 columns
    const int c0 = q * 4;
    uchar4 outv;
    {
        unsigned char tmp[4];
        #pragma unroll
        for (int j = 0; j < 4; ++j) {
            const int s = c0 + j + 17;            // padded window start bit
            const unsigned int lo = sbits[rib][s >> 5];
            const unsigned int hi = sbits[rib][(s >> 5) + 1];
            const unsigned int wnd = __funnelshift_r(lo, hi, s & 31);
            tmp[j] = (unsigned char)__popc(wnd & 0x7FFFFFFFu);
        }
        outv.x = tmp[0]; outv.y = tmp[1]; outv.z = tmp[2]; outv.w = tmp[3];
    }
    *(uchar4*)&g_hsum8[(size_t)(b*HP + r + PAD)*W + c0] = outv;
}

// ---------------------------------------------------------------------------
// K2: vertical running sum (branch-free via zero padding) + fused loss math
// grid (1, H/ROWS, B), block 256, 2 columns per thread
// ---------------------------------------------------------------------------
#define ROWS 16
__global__ void __launch_bounds__(256) k2_main(const float* __restrict__ pred)
{
    const int c  = threadIdx.x * 2;           // even column, c and c+1
    const int r0 = blockIdx.y * ROWS;
    const int b  = blockIdx.z;

    const unsigned char* hs = g_hsum8 + (size_t)b*HP*W + c;   // phys row 0 = logical -PAD
    const unsigned int*  bw = g_bits  + (size_t)b*H*WPR + (c >> 5);
    const float* p0p = pred + (size_t)(2*b)*IMG + c;
    const float* p1p = p0p + IMG;
    const unsigned int sh = c & 31;

    // init window: logical rows r0-15..r0+15 == phys r0..r0+30
    int v0 = 0, v1 = 0;
    #pragma unroll
    for (int j = 0; j < KER; ++j) {
        const uchar2 u = *(const uchar2*)&hs[(r0 + j)*W];
        v0 += u.x; v1 += u.y;
    }

    float a_w = 0.f, a_wb = 0.f, a_i = 0.f, a_c = 0.f;

    #pragma unroll 8
    for (int rr = 0; rr < ROWS; ++rr) {
        const int r = r0 + rr;
        const unsigned int wbits = bw[r*WPR];
        const float2 f0 = *(const float2*)&p0p[r*W];
        const float2 f1 = *(const float2*)&p1p[r*W];

        // slide loads issued early for MLP
        const uchar2 ua = *(const uchar2*)&hs[(r + KER)*W];
        const uchar2 us = *(const uchar2*)&hs[r*W];

        #pragma unroll
        for (int j = 0; j < 2; ++j) {
            const int   vs = j ? v1 : v0;
            const float pooled = (float)vs * (1.0f/961.0f);
            const float mf = (float)((wbits >> (sh + j)) & 1u);
            const float weit = 1.0f + 5.0f * fabsf(pooled - mf);

            const float d = (j ? f1.y : f1.x) - (j ? f0.y : f0.x);
            const float e = __expf(-fabsf(d));
            const float tl = __logf(1.0f + e);
            const float wbce = fmaxf((mf != 0.f) ? -d : d, 0.0f) + tl;
            const float p1 = ((d >= 0.f) ? 1.0f : e) * __fdividef(1.0f, 1.0f + e);

            a_w  += weit;
            a_wb += weit * wbce;
            a_i  += p1 * mf * weit;
            a_c  += (p1 + mf) * weit;
        }
        v0 += (int)ua.x - (int)us.x;
        v1 += (int)ua.y - (int)us.y;
    }

    #pragma unroll
    for (int off = 16; off > 0; off >>= 1) {
        a_w  += __shfl_down_sync(0xffffffffu, a_w,  off);
        a_wb += __shfl_down_sync(0xffffffffu, a_wb, off);
        a_i  += __shfl_down_sync(0xffffffffu, a_i,  off);
        a_c  += __shfl_down_sync(0xffffffffu, a_c,  off);
    }
    if ((threadIdx.x & 31) == 0) {
        atomicAdd(&g_acc[b][0], (double)a_w);
        atomicAdd(&g_acc[b][1], (double)a_wb);
        atomicAdd(&g_acc[b][2], (double)a_i);
        atomicAdd(&g_acc[b][3], (double)a_c);
    }
}

// ---------------------------------------------------------------------------
// K3: combine per-batch losses -> scalar mean
// ---------------------------------------------------------------------------
__global__ void k3_final(float* __restrict__ out)
{
    const int b = threadIdx.x;
    double loss = 0.0;
    if (b < B) {
        const double w  = g_acc[b][0];
        const double wb = g_acc[b][1];
        const double it = g_acc[b][2];
        const double cd = g_acc[b][3];
        const double un = cd - it;
        loss = wb / w + (1.0 - (it + 1.0) / (un + 1.0));
    }
    #pragma unroll
    for (int off = 16; off > 0; off >>= 1)
        loss += __shfl_down_sync(0xffffffffu, loss, off);
    if (b == 0) out[0] = (float)(loss / (double)B);
}

extern "C" void kernel_launch(void* const* d_in, const int* in_sizes, int n_in,
                              void* d_out, int out_size)
{
    const float* pred;
    const int*   mask;
    if (in_sizes[0] == 2*B*IMG) {
        pred = (const float*)d_in[0];
        mask = (const int*)d_in[1];
    } else {
        pred = (const float*)d_in[1];
        mask = (const int*)d_in[0];
    }
    float* out = (float*)d_out;
    (void)n_in; (void)out_size;

    k1_hsum<<<dim3(H/4, B), 512>>>(mask);
    k2_main<<<dim3(1, H/ROWS, B), 256>>>(pred);
    k3_final<<<1, 32>>>(out);
}

// round 6
// speedup vs baseline: 3.2327x; 1.1258x over previous
#include <cuda_runtime.h>
#include <cuda_bf16.h>

#define B 16
#define H 512
#define W 512
#define IMG (H*W)
#define KER 31
#define PAD 15
#define WPR 16                  // u32 words per row of packed mask bits

// Scratch (device globals)
__device__ unsigned int  g_bits[B*H*WPR];     // packed mask bits
__device__ double        g_acc [B][4];        // [weit_sum, wbce_sum, inter, card]

// ---------------------------------------------------------------------------
// K1: pack mask bits only (int4 + shfl-OR). grid (H/4, B), block 512.
// ---------------------------------------------------------------------------
__global__ void __launch_bounds__(512) k1_pack(const int* __restrict__ mask)
{
    const int t   = threadIdx.x;
    const int rib = t >> 7;           // row in block 0..3
    const int q   = t & 127;          // column quad (cols 4q..4q+3)
    const int r   = blockIdx.x*4 + rib;
    const int b   = blockIdx.y;

    if (blockIdx.x == 0 && blockIdx.y == 0 && t < B*4)
        ((double*)g_acc)[t] = 0.0;

    const int4 mv = ((const int4*)mask)[(b*H + r)*(W/4) + q];
    const int m0 = (mv.x == 255) ? 0 : mv.x;
    const int m1 = (mv.y == 255) ? 0 : mv.y;
    const int m2 = (mv.z == 255) ? 0 : mv.z;
    const int m3 = (mv.w == 255) ? 0 : mv.w;
    unsigned int nib = (m0 ? 1u : 0u) | (m1 ? 2u : 0u) | (m2 ? 4u : 0u) | (m3 ? 8u : 0u);

    const int lane = t & 31;
    unsigned int v = nib << ((lane & 7) * 4);
    v |= __shfl_xor_sync(0xffffffffu, v, 1);
    v |= __shfl_xor_sync(0xffffffffu, v, 2);
    v |= __shfl_xor_sync(0xffffffffu, v, 4);
    if ((lane & 7) == 0)
        g_bits[(b*H + r)*WPR + (q >> 3)] = v;
}

// ---------------------------------------------------------------------------
// K2: stage bits in smem, on-the-fly hsum popcounts, vertical running sum,
//     fused loss math. grid (1, H/ROWS, B), block 256, 2 cols/thread.
// ---------------------------------------------------------------------------
#define ROWS 32
#define SROWS (ROWS + 31)       // 63 staged rows (logical r0-15 .. r0+ROWS+15)
#define SW 20                   // smem row stride: [0]=0, [1..16]=data, [17..19]=0

__device__ __forceinline__ int hwin(const unsigned int* row, int ws, int sh)
{
    const unsigned int lo = row[ws];
    const unsigned int hi = row[ws + 1];
    return __popc(__funnelshift_r(lo, hi, sh) & 0x7FFFFFFFu);
}

__global__ void __launch_bounds__(256) k2_main(const float* __restrict__ pred)
{
    __shared__ unsigned int sw[SROWS][SW];
    const int tid = threadIdx.x;
    const int c0  = tid * 2;
    const int r0  = blockIdx.y * ROWS;
    const int b   = blockIdx.z;

    // cooperative staged load of packed bits, zero-padded halo
    for (int i = tid; i < SROWS*SW; i += 256) {
        const int rr = i / SW, w = i % SW;
        const int r = r0 - PAD + rr;
        unsigned int val = 0;
        if (w >= 1 && w <= WPR && r >= 0 && r < H)
            val = g_bits[(b*H + r)*WPR + (w - 1)];
        sw[rr][w] = val;
    }
    __syncthreads();

    // fixed per-column window params (padded bit position s = c + 32 - 15)
    const int s0 = c0 + 17, ws0 = s0 >> 5, sh0 = s0 & 31;
    const int s1 = c0 + 18, ws1 = s1 >> 5, sh1 = s1 & 31;
    const int mw = 1 + (c0 >> 5), msh = c0 & 31;

    const float* p0p = pred + (size_t)(2*b)*IMG + c0;
    const float* p1p = p0p + IMG;

    // init vertical window: logical rows r0-15..r0+15 == staged rows 0..30
    int v0 = 0, v1 = 0;
    #pragma unroll
    for (int j = 0; j < KER; ++j) {
        v0 += hwin(sw[j], ws0, sh0);
        v1 += hwin(sw[j], ws1, sh1);
    }

    float a_w = 0.f, a_wb = 0.f, a_i = 0.f, a_c = 0.f;

    #pragma unroll 4
    for (int rr = 0; rr < ROWS; ++rr) {
        const int r = r0 + rr;
        const unsigned int wbits = sw[rr + PAD][mw];
        const float2 f0 = *(const float2*)&p0p[r*W];
        const float2 f1 = *(const float2*)&p1p[r*W];

        #pragma unroll
        for (int j = 0; j < 2; ++j) {
            const int   vs = j ? v1 : v0;
            const float pooled = (float)vs * (1.0f/961.0f);
            const float mf = (float)((wbits >> (msh + j)) & 1u);
            const float weit = 1.0f + 5.0f * fabsf(pooled - mf);

            const float d = (j ? f1.y : f1.x) - (j ? f0.y : f0.x);
            const float e = __expf(-fabsf(d));
            const float tl = __logf(1.0f + e);
            const float wbce = fmaxf((mf != 0.f) ? -d : d, 0.0f) + tl;
            const float p1 = ((d >= 0.f) ? 1.0f : e) * __fdividef(1.0f, 1.0f + e);

            a_w  += weit;
            a_wb += weit * wbce;
            a_i  += p1 * mf * weit;
            a_c  += (p1 + mf) * weit;
        }
        // slide: add logical r+16 (staged rr+31), drop logical r-15 (staged rr)
        v0 += hwin(sw[rr + 31], ws0, sh0) - hwin(sw[rr], ws0, sh0);
        v1 += hwin(sw[rr + 31], ws1, sh1) - hwin(sw[rr], ws1, sh1);
    }

    #pragma unroll
    for (int off = 16; off > 0; off >>= 1) {
        a_w  += __shfl_down_sync(0xffffffffu, a_w,  off);
        a_wb += __shfl_down_sync(0xffffffffu, a_wb, off);
        a_i  += __shfl_down_sync(0xffffffffu, a_i,  off);
        a_c  += __shfl_down_sync(0xffffffffu, a_c,  off);
    }
    if ((tid & 31) == 0) {
        atomicAdd(&g_acc[b][0], (double)a_w);
        atomicAdd(&g_acc[b][1], (double)a_wb);
        atomicAdd(&g_acc[b][2], (double)a_i);
        atomicAdd(&g_acc[b][3], (double)a_c);
    }
}

// ---------------------------------------------------------------------------
// K3: combine per-batch losses -> scalar mean
// ---------------------------------------------------------------------------
__global__ void k3_final(float* __restrict__ out)
{
    const int b = threadIdx.x;
    double loss = 0.0;
    if (b < B) {
        const double w  = g_acc[b][0];
        const double wb = g_acc[b][1];
        const double it = g_acc[b][2];
        const double cd = g_acc[b][3];
        const double un = cd - it;
        loss = wb / w + (1.0 - (it + 1.0) / (un + 1.0));
    }
    #pragma unroll
    for (int off = 16; off > 0; off >>= 1)
        loss += __shfl_down_sync(0xffffffffu, loss, off);
    if (b == 0) out[0] = (float)(loss / (double)B);
}

extern "C" void kernel_launch(void* const* d_in, const int* in_sizes, int n_in,
                              void* d_out, int out_size)
{
    const float* pred;
    const int*   mask;
    if (in_sizes[0] == 2*B*IMG) {
        pred = (const float*)d_in[0];
        mask = (const int*)d_in[1];
    } else {
        pred = (const float*)d_in[1];
        mask = (const int*)d_in[0];
    }
    float* out = (float*)d_out;
    (void)n_in; (void)out_size;

    k1_pack<<<dim3(H/4, B), 512>>>(mask);
    k2_main<<<dim3(1, H/ROWS, B), 256>>>(pred);
    k3_final<<<1, 32>>>(out);
}